// round 15
// baseline (speedup 1.0000x reference)
#include <cuda_runtime.h>
#include <math.h>

// Problem constants: B=32, N=160, C=3, L=128
// SSIM: VALID 11x11 gaussian -> 150x150 output
// STFT: f=12, s=4 -> p=38 patches/dim, bins u,v in 1..5, weight u*v/25

#define SSIM_BLOCKS (5*5*96)   // 25 tiles x (32 b * 3 c) = 2400
#define STFT_BLOCKS (38*32)    // patch rows x batch = 1216
#define TOTAL_BLOCKS (SSIM_BLOCKS + STFT_BLOCKS + 1)   // +1 = KLD block (bid 0)

#define FXSCALE 1099511627776.0   // 2^40

// Deterministic accumulator: integer atomics commute -> same result any order.
__device__ unsigned long long g_acc = 0ULL;
__device__ unsigned int g_count = 0;     // completion counter (reset by last block)

typedef unsigned long long ull;

// ---- packed f32x2 primitives. RF-banking note: only 2-source forms (ADD2/
// SUB2/MUL2, rt=2 for 2 lanes) are a true 2x; FMA2 (3 pairs -> rt=3) is used
// sparingly. Scalar FFMA with an immediate multiplier (rt=1) is preferred for
// weight convolutions. ----
#define FMA2(d, a, b, c) asm("fma.rn.f32x2 %0, %1, %2, %3;" : "=l"(d) : "l"(a), "l"(b), "l"(c))
#define MUL2(d, a, b)    asm("mul.rn.f32x2 %0, %1, %2;"     : "=l"(d) : "l"(a), "l"(b))
#define ADD2(d, a, b)    asm("add.rn.f32x2 %0, %1, %2;"     : "=l"(d) : "l"(a), "l"(b))
#define SUB2(d, a, b)    asm("sub.rn.f32x2 %0, %1, %2;"     : "=l"(d) : "l"(a), "l"(b))

__device__ __forceinline__ ull pk(float lo, float hi) {
    ull r; asm("mov.b64 %0, {%1, %2};" : "=l"(r) : "f"(lo), "f"(hi)); return r;
}
__device__ __forceinline__ float2 up2(ull v) {
    float2 r; asm("mov.b64 {%0, %1}, %2;" : "=f"(r.x), "=f"(r.y) : "l"(v)); return r;
}
__device__ __forceinline__ float fsqrt_approx(float x) {
    float r; asm("sqrt.approx.f32 %0, %1;" : "=f"(r) : "f"(x)); return r;
}

// gaussian weights (normalized), compile-time immediates
__device__ __forceinline__ constexpr float GNW(int k) {
    constexpr float g[11] = {0.00102838f, 0.00759887f, 0.03600077f, 0.10936069f,
                             0.21300553f, 0.26601172f, 0.21300553f, 0.10936069f,
                             0.03600077f, 0.00759887f, 0.00102838f};
    return g[k];
}

// PACKED 12-point DFT, bins 1..5, both f32 lanes independently.
// Outputs: hr[v] = sum·cos (per lane), g[v] = sum·sin (per lane) (= -im).
__device__ __forceinline__ void dft12_5_p(const ull* __restrict__ v,
                                          ull* __restrict__ hr,
                                          ull* __restrict__ g,
                                          ull p05, ull m05, ull pS3)
{
    ull A1, B1, D1, A2, B2, D2, t1, t2, s1, s2, t, a, b;
    SUB2(A1, v[1], v[5]);  SUB2(A1, A1, v[7]);  ADD2(A1, A1, v[11]);
    SUB2(B1, v[2], v[4]);  SUB2(B1, B1, v[8]);  ADD2(B1, B1, v[10]);
    SUB2(D1, v[0], v[6]);
    ADD2(A2, v[1], v[5]);  SUB2(A2, A2, v[7]);  SUB2(A2, A2, v[11]);
    ADD2(B2, v[2], v[4]);  SUB2(B2, B2, v[8]);  SUB2(B2, B2, v[10]);
    SUB2(D2, v[3], v[9]);
    MUL2(t1, pS3, A1);  MUL2(t2, p05, B1);
    MUL2(s1, p05, A2);  MUL2(s2, pS3, B2);
    // bins 1, 5
    ADD2(t, t1, t2);  ADD2(hr[0], D1, t);
    ADD2(t, s1, s2);  ADD2(g[0], t, D2);
    SUB2(t, t2, t1);  ADD2(hr[4], D1, t);
    SUB2(t, s1, s2);  ADD2(g[4], t, D2);
    // even bins
    ull p0, p3, q1, q2, q4, q5;
    ADD2(p0, v[0], v[6]);  ADD2(p3, v[3], v[9]);
    ADD2(q1, v[1], v[7]);  ADD2(q2, v[2], v[8]);
    ADD2(q4, v[4], v[10]); ADD2(q5, v[5], v[11]);
    ADD2(a, q1, q5);  ADD2(b, q2, q4);  SUB2(a, a, b);
    SUB2(t, p0, p3);  FMA2(hr[1], p05, a, t);
    ADD2(a, q1, q2);  ADD2(b, q4, q5);  SUB2(a, a, b);  MUL2(g[1], pS3, a);
    ADD2(a, v[0], v[4]);  ADD2(a, a, v[8]);
    ADD2(b, v[2], v[6]);  ADD2(b, b, v[10]);  SUB2(hr[2], a, b);
    ADD2(a, v[1], v[5]);  ADD2(a, a, v[9]);
    ADD2(b, v[3], v[7]);  ADD2(b, b, v[11]); SUB2(g[2], a, b);
    ull E0, E1, E2;
    ADD2(E0, p0, p3);  ADD2(E1, q1, q4);  ADD2(E2, q2, q5);
    ADD2(t, E1, E2);   FMA2(hr[3], m05, t, E0);
    SUB2(t, E1, E2);   MUL2(g[3], pS3, t);
}

// atan2, 5-term minimax (A&S 4.4.49, |err| <= 1e-5 rad)
__device__ __forceinline__ float fast_atan2f(float y, float x) {
    float ax = fabsf(x), ay = fabsf(y);
    float mx = fmaxf(ax, ay), mn = fminf(ax, ay);
    float t = __fdividef(mn, mx);
    float s = t*t;
    float p =              0.0208351f;
    p = fmaf(p, s,        -0.0851330f);
    p = fmaf(p, s,         0.1801410f);
    p = fmaf(p, s,        -0.3302995f);
    p = fmaf(p, s,         0.9998660f);
    float r = p * t;
    if (ay > ax)  r = 1.57079632679f - r;
    if (x < 0.f)  r = 3.14159265359f - r;
    return copysignf(r, y);
}

// ---------------------------------------------------------------------------
// Shared memory union. stft H stores (re, +g) per image (g = sin-sum = -im);
// affine phase-B addressing (no swizzle; pad 482; worst conflict N=2).
// Union = 38,560B -> 6 blocks/SM = 231,360B <= 227KB carveout.
// ---------------------------------------------------------------------------
union SmemU {
    float  wred[8];                       // warp partial sums (sync-guarded alias)
    double dred[8];                       // fp64 warp partials (KLD block)
    struct {
        float2 Hin [5][482];              // [u][col] = (re, g) of x_in columns
        float2 Hout[5][482];              // ditto for x_out
    } stft;                               // 38.56 KB
    struct {
        float2 sxy[42][45];               // (x,y) pixel pairs
        float4 hAB[42][33];               // (hx, hy, h_{xx+yy}, h_xy)
    } ssim;                               // 37.3 KB
};

// deterministic 256-thread reduction: shuffle tree + 1 barrier. tid 0 holds sum.
__device__ __forceinline__ float block_reduce_256(float v, float* wbuf, int tid)
{
    #pragma unroll
    for (int o = 16; o > 0; o >>= 1)
        v += __shfl_down_sync(0xffffffffu, v, o);
    if ((tid & 31) == 0) wbuf[tid >> 5] = v;
    __syncthreads();
    float r = 0.f;
    if (tid < 32) {
        r = (tid < 8) ? wbuf[tid] : 0.f;
        #pragma unroll
        for (int o = 4; o > 0; o >>= 1)
            r += __shfl_down_sync(0xffffffffu, r, o);
    }
    return r;
}

// ---------------------------------------------------------------------------
// SSIM tile path (SCALAR FFMA-imm convolutions: rt=1 beats FMA2's rt=3).
// ---------------------------------------------------------------------------
template<bool EDGE>
__device__ __forceinline__ float ssim_tile(SmemU& S,
                                           const float* __restrict__ pin,
                                           const float* __restrict__ pout,
                                           int ox, int oy, int tid)
{
    // ---- load 42x42 tile; incremental (r,cc), no division in loop ----
    {
        int r = tid / 42, cc = tid - r * 42;
        const int base = oy * 480 + ox * 3;
        #pragma unroll
        for (int j = 0; j < 7; j++) {
            if (j < 6 || tid < 228) {                    // 1764 = 6*256 + 228
                float vx = 0.f, vy = 0.f;
                if (!EDGE || ((oy + r) < 160 && (ox + cc) < 160)) {
                    int off = base + r * 480 + cc * 3;
                    vx = pin[off]; vy = pout[off];
                }
                S.ssim.sxy[r][cc] = make_float2(vx, vy);
            }
            cc += 4; r += 6;                             // += 256 elements
            if (cc >= 42) { cc -= 42; r += 1; }
        }
    }
    __syncthreads();

    // ---- horizontal pass: row-major mapping (r = i % 42); scalar FFMA-imm ----
    for (int i = tid; i < 42*8; i += 256) {
        int grp = i / 42;                 // 0..7
        int r   = i - grp * 42;           // 0..41
        int c0  = grp * 4;
        float2 A[4], Bv[4];
        #pragma unroll
        for (int g = 0; g < 4; g++) { A[g] = make_float2(0.f,0.f); Bv[g] = make_float2(0.f,0.f); }
        #pragma unroll
        for (int k = 0; k < 14; k++) {
            float2 xy = S.ssim.sxy[r][c0 + k];
            float ss = fmaf(xy.y, xy.y, xy.x*xy.x);
            float ad = xy.x * xy.y;
            #pragma unroll
            for (int g = 0; g < 4; g++) {
                const int kk = k - g;
                if (kk >= 0 && kk < 11) {
                    const float w = GNW(kk);
                    A[g].x  = fmaf(w, xy.x, A[g].x);
                    A[g].y  = fmaf(w, xy.y, A[g].y);
                    Bv[g].x = fmaf(w, ss,   Bv[g].x);
                    Bv[g].y = fmaf(w, ad,   Bv[g].y);
                }
            }
        }
        #pragma unroll
        for (int g = 0; g < 4; g++)
            S.ssim.hAB[r][c0 + g] = make_float4(A[g].x, A[g].y, Bv[g].x, Bv[g].y);
    }
    __syncthreads();

    // ---- vertical pass: 32 cols x 8 row-groups, 4 outputs/thread; FFMA-imm ----
    const int tx = tid & 31, ty = tid >> 5;
    const int rb = ty * 4;

    float2 aA[4], aB[4];
    #pragma unroll
    for (int g = 0; g < 4; g++) { aA[g] = make_float2(0.f,0.f); aB[g] = make_float2(0.f,0.f); }

    #pragma unroll
    for (int k = 0; k < 14; k++) {
        float4 t = S.ssim.hAB[rb + k][tx];
        #pragma unroll
        for (int g = 0; g < 4; g++) {
            const int kk = k - g;
            if (kk >= 0 && kk < 11) {
                const float w = GNW(kk);
                aA[g].x = fmaf(w, t.x, aA[g].x);
                aA[g].y = fmaf(w, t.y, aA[g].y);
                aB[g].x = fmaf(w, t.z, aB[g].x);
                aB[g].y = fmaf(w, t.w, aB[g].y);
            }
        }
    }

    float val = 0.f;
    #pragma unroll
    for (int g = 0; g < 4; g++) {
        bool ok = true;
        if (EDGE) ok = ((ox + tx) < 150) && ((oy + rb + g) < 150);
        if (ok) {
            const float C1 = 1e-4f, C2 = 9e-4f;
            float mx = aA[g].x, my = aA[g].y;
            float vsum = aB[g].x - mx*mx - my*my;        // var_x + var_y
            float cov  = aB[g].y - mx*my;
            float num = (2.f*mx*my + C1) * (2.f*cov + C2);
            float den = (mx*mx + my*my + C1) * (vsum + C2);
            val += __fdividef(num, den);                 // lum*cs, one divide
        }
    }
    return val;
}

// ---------------------------------------------------------------------------
// Single fused kernel: bid 0 -> KLD; bid 1..STFT_BLOCKS -> stft; rest -> ssim.
// __launch_bounds__(256, 6): regs capped at 42 so 6 blocks/SM fit (smem also
// fits: 38.56KB x 6 = 226KB <= 227KB carveout). Occupancy 62.5% -> 75% cap.
// ---------------------------------------------------------------------------
__global__ void __launch_bounds__(256, 6) fused_kernel(const float* __restrict__ xin,
                                                       const float* __restrict__ xout,
                                                       const float* __restrict__ mean,
                                                       const float* __restrict__ logvar,
                                                       float* __restrict__ out)
{
    __shared__ SmemU S;
    const int tid = threadIdx.x;
    const int bid = blockIdx.x;

    long long q = 0;     // this block's fixed-point partial (valid in tid 0)

    if (bid == 0) {
        // =================== KLD block ===================
        const double K_KLD = -0.5 / 32.0;
        const float4* m4 = reinterpret_cast<const float4*>(mean);
        const float4* l4 = reinterpret_cast<const float4*>(logvar);
        double acc = 0.0;
        #pragma unroll
        for (int j = 0; j < 4; j++) {
            int i = tid + j * 256;
            float4 lv = l4[i], mm = m4[i];
            float s = (1.0f + lv.x - __expf(lv.x) - mm.x*mm.x)
                    + (1.0f + lv.y - __expf(lv.y) - mm.y*mm.y)
                    + (1.0f + lv.z - __expf(lv.z) - mm.z*mm.z)
                    + (1.0f + lv.w - __expf(lv.w) - mm.w*mm.w);
            acc += (double)s * K_KLD;
        }
        #pragma unroll
        for (int o = 16; o > 0; o >>= 1)
            acc += __shfl_down_sync(0xffffffffu, acc, o);
        if ((tid & 31) == 0) S.dred[tid >> 5] = acc;
        __syncthreads();
        if (tid < 32) {
            double v = (tid < 8) ? S.dred[tid] : 0.0;
            #pragma unroll
            for (int o = 4; o > 0; o >>= 1)
                v += __shfl_down_sync(0xffffffffu, v, o);
            if (tid == 0) q = __double2ll_rn(v * FXSCALE);
        }

    } else if (bid <= STFT_BLOCKS) {
        // =================== STFT path ===================
        const int sbid = bid - 1;
        const int b = sbid / 38;
        const int prow = sbid - b * 38;   // image rows prow*4 .. prow*4+11

        const float* pin  = xin  + ((long)b * 160 + (long)prow * 4) * 480;
        const float* pout = xout + ((long)b * 160 + (long)prow * 4) * 480;

        const ull p05 = pk(0.5f, 0.5f);
        const ull m05 = pk(-0.5f, -0.5f);
        const ull pS3 = pk(0.86602540378f, 0.86602540378f);

        // Phase A: ONE packed column DFT across (in,out) images.
        for (int e = tid; e < 480; e += 256) {
            ull v[12];
            #pragma unroll
            for (int y = 0; y < 12; y++)
                v[y] = pk(pin[y*480 + e], pout[y*480 + e]);
            ull hr[5], g[5];
            dft12_5_p(v, hr, g, p05, m05, pS3);
            #pragma unroll
            for (int u = 0; u < 5; u++) {
                float2 h = up2(hr[u]), gg = up2(g[u]);
                S.stft.Hin [u][e] = make_float2(h.x, gg.x);
                S.stft.Hout[u][e] = make_float2(h.y, gg.y);
            }
        }
        __syncthreads();

        // Phase B: 570 items. Packed DFT on (re,g) columns per image.
        // h = re - i*g. F.re = Pa - Gb; F.im = -(Ga + Pb).
        float acc = 0.f;
        for (int id = tid; id < 570; id += 256) {
            const int u = id / 114;       // 0..4  (bin u+1)
            const int m = id - u*114;     // 0..113 = j*3 + c
            const int cch = m % 3;
            const int e0 = 4*m - 3*cch;   // = 12j + c

            float Fir[5], Fii[5], For[5], Foi[5];
            {
                ull c[12];
                #pragma unroll
                for (int x = 0; x < 12; x++)
                    c[x] = *reinterpret_cast<const ull*>(&S.stft.Hin[u][e0 + 3*x]);
                ull P[5], G[5];
                dft12_5_p(c, P, G, p05, m05, pS3);
                #pragma unroll
                for (int v = 0; v < 5; v++) {
                    float2 pv = up2(P[v]), gv = up2(G[v]);
                    Fir[v] = pv.x - gv.y;
                    Fii[v] = -(gv.x + pv.y);
                }
            }
            {
                ull c[12];
                #pragma unroll
                for (int x = 0; x < 12; x++)
                    c[x] = *reinterpret_cast<const ull*>(&S.stft.Hout[u][e0 + 3*x]);
                ull P[5], G[5];
                dft12_5_p(c, P, G, p05, m05, pS3);
                #pragma unroll
                for (int v = 0; v < 5; v++) {
                    float2 pv = up2(P[v]), gv = up2(G[v]);
                    For[v] = pv.x - gv.y;
                    Foi[v] = -(gv.x + pv.y);
                }
            }

            const float wu = (float)(u + 1) * (1.f / 25.f);
            #pragma unroll
            for (int v = 1; v <= 5; v++) {
                const int vi = v - 1;
                float angi = fast_atan2f(Fii[vi], Fir[vi] + 1e-8f);
                float ango = fast_atan2f(Foi[vi], For[vi] + 1e-8f);
                float m2i = fmaf(Fir[vi], Fir[vi], Fii[vi]*Fii[vi]);
                float m2o = fmaf(For[vi], For[vi], Foi[vi]*Foi[vi]);
                float magi = fsqrt_approx(m2i);
                float mago = fsqrt_approx(m2o);
                acc = fmaf((float)v * wu, fabsf(ango - angi) + fabsf(mago - magi), acc);
            }
        }

        __syncthreads();                  // wred aliases H: all H reads must finish
        float tot = block_reduce_256(acc, S.wred, tid);
        if (tid == 0)
            q = __double2ll_rn((double)tot * (1e-4 / 32.0) * FXSCALE);

    } else {
        // =================== SSIM path ===================
        const int idx = bid - 1 - STFT_BLOCKS;
        const int bz = idx / 25;          // b*3 + c
        const int r25 = idx - bz*25;
        const int by = r25 / 5, bx = r25 - by*5;
        const int c  = bz % 3, b = bz / 3;
        const int ox = bx * 32, oy = by * 32;

        const float* pin  = xin  + (size_t)b * (160*160*3) + c;
        const float* pout = xout + (size_t)b * (160*160*3) + c;

        float val;
        if (bx < 4 && by < 4)
            val = ssim_tile<false>(S, pin, pout, ox, oy, tid);
        else
            val = ssim_tile<true >(S, pin, pout, ox, oy, tid);

        float tot = block_reduce_256(val, S.wred, tid);
        if (tid == 0)
            q = __double2ll_rn((double)tot * (1.0 / (32.0 * 150.0 * 150.0 * 3.0)) * FXSCALE);
    }

    // ---- publish + last-block finalize (tid 0 only) ----
    if (tid == 0) {
        atomicAdd(&g_acc, (unsigned long long)q);
        __threadfence();                  // order g_acc add before counter add
        unsigned int old = atomicAdd(&g_count, 1u);
        if (old == TOTAL_BLOCKS - 1) {    // I'm the last block
            unsigned long long raw = atomicExch(&g_acc, 0ULL);  // consume + reset
            out[0] = (float)((double)(long long)raw * (1.0 / FXSCALE));
            g_count = 0;                  // reset for next graph replay
        }
    }
}

// ---------------------------------------------------------------------------
extern "C" void kernel_launch(void* const* d_in, const int* in_sizes, int n_in,
                              void* d_out, int out_size)
{
    const float* mean   = (const float*)d_in[0];
    const float* logvar = (const float*)d_in[1];
    const float* xin    = (const float*)d_in[2];
    const float* xout   = (const float*)d_in[3];
    float* out = (float*)d_out;

    fused_kernel<<<TOTAL_BLOCKS, 256>>>(xin, xout, mean, logvar, out);
}

// round 16
// speedup vs baseline: 1.2583x; 1.2583x over previous
#include <cuda_runtime.h>
#include <math.h>

// Problem constants: B=32, N=160, C=3, L=128
// SSIM: VALID 11x11 gaussian -> 150x150 output
// STFT: f=12, s=4 -> p=38 patches/dim, bins u,v in 1..5, weight u*v/25

#define SSIM_BLOCKS (5*5*96)   // 25 tiles x (32 b * 3 c) = 2400
#define STFT_BLOCKS (38*32)    // patch rows x batch = 1216
#define TOTAL_BLOCKS (SSIM_BLOCKS + STFT_BLOCKS + 1)   // +1 = KLD block (bid 0)

#define FXSCALE 1099511627776.0   // 2^40

// Deterministic accumulator: integer atomics commute -> same result any order.
__device__ unsigned long long g_acc = 0ULL;
__device__ unsigned int g_count = 0;     // completion counter (reset by last block)

typedef unsigned long long ull;

// ---- packed f32x2 primitives. RF-banking note: only 2-source forms (ADD2/
// SUB2/MUL2, rt=2 for 2 lanes) are a true 2x; FMA2 (3 pairs -> rt=3) is used
// sparingly. Scalar FFMA with an immediate multiplier (rt=1) is preferred for
// weight convolutions. ----
#define FMA2(d, a, b, c) asm("fma.rn.f32x2 %0, %1, %2, %3;" : "=l"(d) : "l"(a), "l"(b), "l"(c))
#define MUL2(d, a, b)    asm("mul.rn.f32x2 %0, %1, %2;"     : "=l"(d) : "l"(a), "l"(b))
#define ADD2(d, a, b)    asm("add.rn.f32x2 %0, %1, %2;"     : "=l"(d) : "l"(a), "l"(b))
#define SUB2(d, a, b)    asm("sub.rn.f32x2 %0, %1, %2;"     : "=l"(d) : "l"(a), "l"(b))

__device__ __forceinline__ ull pk(float lo, float hi) {
    ull r; asm("mov.b64 %0, {%1, %2};" : "=l"(r) : "f"(lo), "f"(hi)); return r;
}
__device__ __forceinline__ float2 up2(ull v) {
    float2 r; asm("mov.b64 {%0, %1}, %2;" : "=f"(r.x), "=f"(r.y) : "l"(v)); return r;
}
__device__ __forceinline__ float fsqrt_approx(float x) {
    float r; asm("sqrt.approx.f32 %0, %1;" : "=f"(r) : "f"(x)); return r;
}

// gaussian weights (normalized), compile-time immediates
__device__ __forceinline__ constexpr float GNW(int k) {
    constexpr float g[11] = {0.00102838f, 0.00759887f, 0.03600077f, 0.10936069f,
                             0.21300553f, 0.26601172f, 0.21300553f, 0.10936069f,
                             0.03600077f, 0.00759887f, 0.00102838f};
    return g[k];
}

// PACKED 12-point DFT, bins 1..5, both f32 lanes independently.
// Outputs: hr[v] = sum·cos (per lane), g[v] = sum·sin (per lane) (= -im).
__device__ __forceinline__ void dft12_5_p(const ull* __restrict__ v,
                                          ull* __restrict__ hr,
                                          ull* __restrict__ g,
                                          ull p05, ull m05, ull pS3)
{
    ull A1, B1, D1, A2, B2, D2, t1, t2, s1, s2, t, a, b;
    SUB2(A1, v[1], v[5]);  SUB2(A1, A1, v[7]);  ADD2(A1, A1, v[11]);
    SUB2(B1, v[2], v[4]);  SUB2(B1, B1, v[8]);  ADD2(B1, B1, v[10]);
    SUB2(D1, v[0], v[6]);
    ADD2(A2, v[1], v[5]);  SUB2(A2, A2, v[7]);  SUB2(A2, A2, v[11]);
    ADD2(B2, v[2], v[4]);  SUB2(B2, B2, v[8]);  SUB2(B2, B2, v[10]);
    SUB2(D2, v[3], v[9]);
    MUL2(t1, pS3, A1);  MUL2(t2, p05, B1);
    MUL2(s1, p05, A2);  MUL2(s2, pS3, B2);
    // bins 1, 5
    ADD2(t, t1, t2);  ADD2(hr[0], D1, t);
    ADD2(t, s1, s2);  ADD2(g[0], t, D2);
    SUB2(t, t2, t1);  ADD2(hr[4], D1, t);
    SUB2(t, s1, s2);  ADD2(g[4], t, D2);
    // even bins
    ull p0, p3, q1, q2, q4, q5;
    ADD2(p0, v[0], v[6]);  ADD2(p3, v[3], v[9]);
    ADD2(q1, v[1], v[7]);  ADD2(q2, v[2], v[8]);
    ADD2(q4, v[4], v[10]); ADD2(q5, v[5], v[11]);
    ADD2(a, q1, q5);  ADD2(b, q2, q4);  SUB2(a, a, b);
    SUB2(t, p0, p3);  FMA2(hr[1], p05, a, t);
    ADD2(a, q1, q2);  ADD2(b, q4, q5);  SUB2(a, a, b);  MUL2(g[1], pS3, a);
    ADD2(a, v[0], v[4]);  ADD2(a, a, v[8]);
    ADD2(b, v[2], v[6]);  ADD2(b, b, v[10]);  SUB2(hr[2], a, b);
    ADD2(a, v[1], v[5]);  ADD2(a, a, v[9]);
    ADD2(b, v[3], v[7]);  ADD2(b, b, v[11]); SUB2(g[2], a, b);
    ull E0, E1, E2;
    ADD2(E0, p0, p3);  ADD2(E1, q1, q4);  ADD2(E2, q2, q5);
    ADD2(t, E1, E2);   FMA2(hr[3], m05, t, E0);
    SUB2(t, E1, E2);   MUL2(g[3], pS3, t);
}

// atan2, 5-term minimax (A&S 4.4.49, |err| <= 1e-5 rad)
__device__ __forceinline__ float fast_atan2f(float y, float x) {
    float ax = fabsf(x), ay = fabsf(y);
    float mx = fmaxf(ax, ay), mn = fminf(ax, ay);
    float t = __fdividef(mn, mx);
    float s = t*t;
    float p =              0.0208351f;
    p = fmaf(p, s,        -0.0851330f);
    p = fmaf(p, s,         0.1801410f);
    p = fmaf(p, s,        -0.3302995f);
    p = fmaf(p, s,         0.9998660f);
    float r = p * t;
    if (ay > ax)  r = 1.57079632679f - r;
    if (x < 0.f)  r = 3.14159265359f - r;
    return copysignf(r, y);
}

// ---------------------------------------------------------------------------
// Shared memory union. stft H stores (re, +g) per image (g = sin-sum = -im);
// affine phase-B addressing (no swizzle; pad 482; worst conflict N=2).
// ---------------------------------------------------------------------------
union SmemU {
    float  wred[8];                       // warp partial sums (sync-guarded alias)
    double dred[8];                       // fp64 warp partials (KLD block)
    struct {
        float2 Hin [5][482];              // [u][col] = (re, g) of x_in columns
        float2 Hout[5][482];              // ditto for x_out
    } stft;                               // 38.56 KB
    struct {
        float2 sxy[42][45];               // (x,y) pixel pairs
        float4 hAB[42][33];               // (hx, hy, h_{xx+yy}, h_xy)
    } ssim;                               // 37.3 KB
};

// deterministic 256-thread reduction: shuffle tree + 1 barrier. tid 0 holds sum.
__device__ __forceinline__ float block_reduce_256(float v, float* wbuf, int tid)
{
    #pragma unroll
    for (int o = 16; o > 0; o >>= 1)
        v += __shfl_down_sync(0xffffffffu, v, o);
    if ((tid & 31) == 0) wbuf[tid >> 5] = v;
    __syncthreads();
    float r = 0.f;
    if (tid < 32) {
        r = (tid < 8) ? wbuf[tid] : 0.f;
        #pragma unroll
        for (int o = 4; o > 0; o >>= 1)
            r += __shfl_down_sync(0xffffffffu, r, o);
    }
    return r;
}

// ---------------------------------------------------------------------------
// SSIM tile path (SCALAR FFMA-imm convolutions: rt=1 beats FMA2's rt=3).
// ---------------------------------------------------------------------------
template<bool EDGE>
__device__ __forceinline__ float ssim_tile(SmemU& S,
                                           const float* __restrict__ pin,
                                           const float* __restrict__ pout,
                                           int ox, int oy, int tid)
{
    // ---- load 42x42 tile; incremental (r,cc), no division in loop ----
    {
        int r = tid / 42, cc = tid - r * 42;
        const int base = oy * 480 + ox * 3;
        #pragma unroll
        for (int j = 0; j < 7; j++) {
            if (j < 6 || tid < 228) {                    // 1764 = 6*256 + 228
                float vx = 0.f, vy = 0.f;
                if (!EDGE || ((oy + r) < 160 && (ox + cc) < 160)) {
                    int off = base + r * 480 + cc * 3;
                    vx = pin[off]; vy = pout[off];
                }
                S.ssim.sxy[r][cc] = make_float2(vx, vy);
            }
            cc += 4; r += 6;                             // += 256 elements
            if (cc >= 42) { cc -= 42; r += 1; }
        }
    }
    __syncthreads();

    // ---- horizontal pass: row-major mapping (r = i % 42); scalar FFMA-imm ----
    for (int i = tid; i < 42*8; i += 256) {
        int grp = i / 42;                 // 0..7
        int r   = i - grp * 42;           // 0..41
        int c0  = grp * 4;
        float2 A[4], Bv[4];
        #pragma unroll
        for (int g = 0; g < 4; g++) { A[g] = make_float2(0.f,0.f); Bv[g] = make_float2(0.f,0.f); }
        #pragma unroll
        for (int k = 0; k < 14; k++) {
            float2 xy = S.ssim.sxy[r][c0 + k];
            float ss = fmaf(xy.y, xy.y, xy.x*xy.x);
            float ad = xy.x * xy.y;
            #pragma unroll
            for (int g = 0; g < 4; g++) {
                const int kk = k - g;
                if (kk >= 0 && kk < 11) {
                    const float w = GNW(kk);
                    A[g].x  = fmaf(w, xy.x, A[g].x);
                    A[g].y  = fmaf(w, xy.y, A[g].y);
                    Bv[g].x = fmaf(w, ss,   Bv[g].x);
                    Bv[g].y = fmaf(w, ad,   Bv[g].y);
                }
            }
        }
        #pragma unroll
        for (int g = 0; g < 4; g++)
            S.ssim.hAB[r][c0 + g] = make_float4(A[g].x, A[g].y, Bv[g].x, Bv[g].y);
    }
    __syncthreads();

    // ---- vertical pass: 32 cols x 8 row-groups, 4 outputs/thread; FFMA-imm ----
    const int tx = tid & 31, ty = tid >> 5;
    const int rb = ty * 4;

    float2 aA[4], aB[4];
    #pragma unroll
    for (int g = 0; g < 4; g++) { aA[g] = make_float2(0.f,0.f); aB[g] = make_float2(0.f,0.f); }

    #pragma unroll
    for (int k = 0; k < 14; k++) {
        float4 t = S.ssim.hAB[rb + k][tx];
        #pragma unroll
        for (int g = 0; g < 4; g++) {
            const int kk = k - g;
            if (kk >= 0 && kk < 11) {
                const float w = GNW(kk);
                aA[g].x = fmaf(w, t.x, aA[g].x);
                aA[g].y = fmaf(w, t.y, aA[g].y);
                aB[g].x = fmaf(w, t.z, aB[g].x);
                aB[g].y = fmaf(w, t.w, aB[g].y);
            }
        }
    }

    float val = 0.f;
    #pragma unroll
    for (int g = 0; g < 4; g++) {
        bool ok = true;
        if (EDGE) ok = ((ox + tx) < 150) && ((oy + rb + g) < 150);
        if (ok) {
            const float C1 = 1e-4f, C2 = 9e-4f;
            float mx = aA[g].x, my = aA[g].y;
            float vsum = aB[g].x - mx*mx - my*my;        // var_x + var_y
            float cov  = aB[g].y - mx*my;
            float num = (2.f*mx*my + C1) * (2.f*cov + C2);
            float den = (mx*mx + my*my + C1) * (vsum + C2);
            val += __fdividef(num, den);                 // lum*cs, one divide
        }
    }
    return val;
}

// ---------------------------------------------------------------------------
// Single fused kernel: bid 0 -> KLD; bid 1..STFT_BLOCKS -> stft; rest -> ssim.
// __launch_bounds__(256, 5): the verified resource optimum. 6 blocks/SM
// (regs<=42) was measured to SPILL (R15: L2 18.8->34.4%, +10.5us).
// ---------------------------------------------------------------------------
__global__ void __launch_bounds__(256, 5) fused_kernel(const float* __restrict__ xin,
                                                       const float* __restrict__ xout,
                                                       const float* __restrict__ mean,
                                                       const float* __restrict__ logvar,
                                                       float* __restrict__ out)
{
    __shared__ SmemU S;
    const int tid = threadIdx.x;
    const int bid = blockIdx.x;

    long long q = 0;     // this block's fixed-point partial (valid in tid 0)

    if (bid == 0) {
        // =================== KLD block ===================
        const double K_KLD = -0.5 / 32.0;
        const float4* m4 = reinterpret_cast<const float4*>(mean);
        const float4* l4 = reinterpret_cast<const float4*>(logvar);
        double acc = 0.0;
        #pragma unroll
        for (int j = 0; j < 4; j++) {
            int i = tid + j * 256;
            float4 lv = l4[i], mm = m4[i];
            float s = (1.0f + lv.x - __expf(lv.x) - mm.x*mm.x)
                    + (1.0f + lv.y - __expf(lv.y) - mm.y*mm.y)
                    + (1.0f + lv.z - __expf(lv.z) - mm.z*mm.z)
                    + (1.0f + lv.w - __expf(lv.w) - mm.w*mm.w);
            acc += (double)s * K_KLD;
        }
        #pragma unroll
        for (int o = 16; o > 0; o >>= 1)
            acc += __shfl_down_sync(0xffffffffu, acc, o);
        if ((tid & 31) == 0) S.dred[tid >> 5] = acc;
        __syncthreads();
        if (tid < 32) {
            double v = (tid < 8) ? S.dred[tid] : 0.0;
            #pragma unroll
            for (int o = 4; o > 0; o >>= 1)
                v += __shfl_down_sync(0xffffffffu, v, o);
            if (tid == 0) q = __double2ll_rn(v * FXSCALE);
        }

    } else if (bid <= STFT_BLOCKS) {
        // =================== STFT path ===================
        const int sbid = bid - 1;
        const int b = sbid / 38;
        const int prow = sbid - b * 38;   // image rows prow*4 .. prow*4+11

        const float* pin  = xin  + ((long)b * 160 + (long)prow * 4) * 480;
        const float* pout = xout + ((long)b * 160 + (long)prow * 4) * 480;

        const ull p05 = pk(0.5f, 0.5f);
        const ull m05 = pk(-0.5f, -0.5f);
        const ull pS3 = pk(0.86602540378f, 0.86602540378f);

        // Phase A: ONE packed column DFT across (in,out) images.
        for (int e = tid; e < 480; e += 256) {
            ull v[12];
            #pragma unroll
            for (int y = 0; y < 12; y++)
                v[y] = pk(pin[y*480 + e], pout[y*480 + e]);
            ull hr[5], g[5];
            dft12_5_p(v, hr, g, p05, m05, pS3);
            #pragma unroll
            for (int u = 0; u < 5; u++) {
                float2 h = up2(hr[u]), gg = up2(g[u]);
                S.stft.Hin [u][e] = make_float2(h.x, gg.x);
                S.stft.Hout[u][e] = make_float2(h.y, gg.y);
            }
        }
        __syncthreads();

        // Phase B: 570 items. Packed DFT on (re,g) columns per image.
        // h = re - i*g. F.re = Pa - Gb; F.im = -(Ga + Pb).
        float acc = 0.f;
        for (int id = tid; id < 570; id += 256) {
            const int u = id / 114;       // 0..4  (bin u+1)
            const int m = id - u*114;     // 0..113 = j*3 + c
            const int cch = m % 3;
            const int e0 = 4*m - 3*cch;   // = 12j + c

            float Fir[5], Fii[5], For[5], Foi[5];
            {
                ull c[12];
                #pragma unroll
                for (int x = 0; x < 12; x++)
                    c[x] = *reinterpret_cast<const ull*>(&S.stft.Hin[u][e0 + 3*x]);
                ull P[5], G[5];
                dft12_5_p(c, P, G, p05, m05, pS3);
                #pragma unroll
                for (int v = 0; v < 5; v++) {
                    float2 pv = up2(P[v]), gv = up2(G[v]);
                    Fir[v] = pv.x - gv.y;
                    Fii[v] = -(gv.x + pv.y);
                }
            }
            {
                ull c[12];
                #pragma unroll
                for (int x = 0; x < 12; x++)
                    c[x] = *reinterpret_cast<const ull*>(&S.stft.Hout[u][e0 + 3*x]);
                ull P[5], G[5];
                dft12_5_p(c, P, G, p05, m05, pS3);
                #pragma unroll
                for (int v = 0; v < 5; v++) {
                    float2 pv = up2(P[v]), gv = up2(G[v]);
                    For[v] = pv.x - gv.y;
                    Foi[v] = -(gv.x + pv.y);
                }
            }

            const float wu = (float)(u + 1) * (1.f / 25.f);
            #pragma unroll
            for (int v = 1; v <= 5; v++) {
                const int vi = v - 1;
                float angi = fast_atan2f(Fii[vi], Fir[vi] + 1e-8f);
                float ango = fast_atan2f(Foi[vi], For[vi] + 1e-8f);
                float m2i = fmaf(Fir[vi], Fir[vi], Fii[vi]*Fii[vi]);
                float m2o = fmaf(For[vi], For[vi], Foi[vi]*Foi[vi]);
                float magi = fsqrt_approx(m2i);
                float mago = fsqrt_approx(m2o);
                acc = fmaf((float)v * wu, fabsf(ango - angi) + fabsf(mago - magi), acc);
            }
        }

        __syncthreads();                  // wred aliases H: all H reads must finish
        float tot = block_reduce_256(acc, S.wred, tid);
        if (tid == 0)
            q = __double2ll_rn((double)tot * (1e-4 / 32.0) * FXSCALE);

    } else {
        // =================== SSIM path ===================
        const int idx = bid - 1 - STFT_BLOCKS;
        const int bz = idx / 25;          // b*3 + c
        const int r25 = idx - bz*25;
        const int by = r25 / 5, bx = r25 - by*5;
        const int c  = bz % 3, b = bz / 3;
        const int ox = bx * 32, oy = by * 32;

        const float* pin  = xin  + (size_t)b * (160*160*3) + c;
        const float* pout = xout + (size_t)b * (160*160*3) + c;

        float val;
        if (bx < 4 && by < 4)
            val = ssim_tile<false>(S, pin, pout, ox, oy, tid);
        else
            val = ssim_tile<true >(S, pin, pout, ox, oy, tid);

        float tot = block_reduce_256(val, S.wred, tid);
        if (tid == 0)
            q = __double2ll_rn((double)tot * (1.0 / (32.0 * 150.0 * 150.0 * 3.0)) * FXSCALE);
    }

    // ---- publish + last-block finalize (tid 0 only) ----
    if (tid == 0) {
        atomicAdd(&g_acc, (unsigned long long)q);
        __threadfence();                  // order g_acc add before counter add
        unsigned int old = atomicAdd(&g_count, 1u);
        if (old == TOTAL_BLOCKS - 1) {    // I'm the last block
            unsigned long long raw = atomicExch(&g_acc, 0ULL);  // consume + reset
            out[0] = (float)((double)(long long)raw * (1.0 / FXSCALE));
            g_count = 0;                  // reset for next graph replay
        }
    }
}

// ---------------------------------------------------------------------------
extern "C" void kernel_launch(void* const* d_in, const int* in_sizes, int n_in,
                              void* d_out, int out_size)
{
    const float* mean   = (const float*)d_in[0];
    const float* logvar = (const float*)d_in[1];
    const float* xin    = (const float*)d_in[2];
    const float* xout   = (const float*)d_in[3];
    float* out = (float*)d_out;

    fused_kernel<<<TOTAL_BLOCKS, 256>>>(xin, xout, mean, logvar, out);
}